// round 16
// baseline (speedup 1.0000x reference)
#include <cuda_runtime.h>
#include <cuda_bf16.h>
#include <cuda_fp16.h>

#define NN 50000
#define NE 800000
#define EE (NE + NN)
#define NG 32
#define KMAX 16
#define FIN 128
#define HID 64
#define HEADS 4
#define HC 256          // HEADS*HID
#define NP1 (NN + 1)
#define CAP 160
#define NB_SCAN ((NN + 255) / 256)
#define SCH 8
#define CHUNK (NN / SCH)   // 6250
#define CSRGRID 784        // 784*256*4 >= NE edges; 200K threads co-resident

// ---------------- scratch ----------------
__device__ unsigned char g_h1f8[NN * HC];    // x@W1 in fp8 e4m3 (gather operand)
__device__ float         g_h1  [NN * HC];    // after GAT1 + relu (GEMM2 input)
__device__ __nv_bfloat16 g_h2bf[NN * HID];   // h1@W2 in bf16 (gather operand)
__device__ float         g_h2  [NN * HID];   // after GAT2 (+b2)
__device__ float         g_as1 [NN * HEADS];
__device__ float         g_ad1 [NN * HEADS];
__device__ float         g_as2 [NN];
__device__ float         g_ad2 [NN];
__device__ float         g_scores[NN];
__device__ float         g_stop  [NG];
__device__ int           g_ei64;
__device__ int           g_maskmode;         // 0=uint8, 1=int32, 2=float32

// CSR scratch
__device__ int g_cnt [NN];
__device__ int g_off [NN];
__device__ int g_woff[NN];
__device__ int g_csrc[EE];
__device__ int g_bsum[NB_SCAN];
__device__ int g_bsumoff[NB_SCAN];

// grid barrier (monotonic generation: safe across graph replays and ncu replay)
__device__ unsigned g_bargen = 0;
__device__ unsigned g_barcnt = 0;

// softmax partials
__device__ float g_pm[NG * SCH];
__device__ float g_ps[NG * SCH];
__device__ float g_smx[NG];
__device__ float g_sinv[NG];

// ---------------- helpers ----------------
__device__ __forceinline__ float lrelu(float a) { return a > 0.f ? a : 0.2f * a; }

__device__ __forceinline__ float warp_sum(float v) {
#pragma unroll
    for (int o = 16; o; o >>= 1) v += __shfl_xor_sync(0xffffffffu, v, o);
    return v;
}
__device__ __forceinline__ float warp_max(float v) {
#pragma unroll
    for (int o = 16; o; o >>= 1) v = fmaxf(v, __shfl_xor_sync(0xffffffffu, v, o));
    return v;
}

__device__ __forceinline__ unsigned f2tf(float f) {
    unsigned u;
    asm("cvt.rna.tf32.f32 %0, %1;" : "=r"(u) : "f"(f));
    return u;
}
__device__ __forceinline__ void mma_tf32(float* c, const unsigned* a, const unsigned* b) {
    asm volatile(
        "mma.sync.aligned.m16n8k8.row.col.f32.tf32.tf32.f32 "
        "{%0,%1,%2,%3},{%4,%5,%6,%7},{%8,%9},{%0,%1,%2,%3};"
        : "+f"(c[0]), "+f"(c[1]), "+f"(c[2]), "+f"(c[3])
        : "r"(a[0]), "r"(a[1]), "r"(a[2]), "r"(a[3]), "r"(b[0]), "r"(b[1]));
}

// fp8 e4m3 pack: returns (fp8(hi)<<8)|fp8(lo)
__device__ __forceinline__ unsigned short f2_to_fp8x2(float hi, float lo) {
    unsigned short r;
    asm("cvt.rn.satfinite.e4m3x2.f32 %0, %1, %2;" : "=h"(r) : "f"(hi), "f"(lo));
    return r;
}
// fp8x2 (low 16 bits) -> half2
__device__ __forceinline__ __half2 fp8x2_to_h2(unsigned v) {
    unsigned r;
    unsigned short s = (unsigned short)v;
    asm("cvt.rn.f16x2.e4m3x2 %0, %1;" : "=r"(r) : "h"(s));
    return *(__half2*)&r;
}

__device__ __forceinline__ void grid_barrier() {
    __syncthreads();
    if (threadIdx.x == 0) {
        __threadfence();
        unsigned my = atomicAdd(&g_bargen, 0u);
        if (atomicAdd(&g_barcnt, 1u) == gridDim.x - 1) {
            atomicExch(&g_barcnt, 0u);
            atomicAdd(&g_bargen, 1u);
        } else {
            while (atomicAdd(&g_bargen, 0u) == my) {}
        }
        __threadfence();
    }
    __syncthreads();
}

// ---------------- CSR build, kernel 1: detect + init cnt + histogram ----------------
__global__ void __launch_bounds__(256) csr_build1(const int* __restrict__ ei,
                                                  const unsigned* __restrict__ m) {
    int tid = blockIdx.x * 256 + threadIdx.x;
    if (blockIdx.x == 0 && threadIdx.x < 32) {
        int lane = threadIdx.x;
        int f32 = 0, multi = 0;
        for (int i = lane; i < 2048; i += 32) {
            unsigned w = m[i];
            if (w == 0x3F800000u) f32 = 1;
            else if (w > 1u) multi = 1;
        }
        f32 = __any_sync(0xffffffffu, f32);
        multi = __any_sync(0xffffffffu, multi);
        if (lane == 0) {
            g_maskmode = f32 ? 2 : (multi ? 0 : 1);
            const unsigned* eu = (const unsigned*)ei;
            unsigned o = eu[1] | eu[3] | eu[5] | eu[7] | eu[9] | eu[11] | eu[13] | eu[15];
            g_ei64 = (o == 0u) ? 1 : 0;
        }
    }
    for (int i = tid; i < NN; i += CSRGRID * 256) g_cnt[i] = 1;   // self-loop pre-seeded
    grid_barrier();
    int e4 = tid * 4;
    if (e4 < NE) {
        int d0, d1, d2, d3;
        if (g_ei64) {
            int4 a = *(const int4*)&ei[2 * (NE + e4)];
            int4 b = *(const int4*)&ei[2 * (NE + e4) + 4];
            d0 = a.x; d1 = a.z; d2 = b.x; d3 = b.z;
        } else {
            int4 d = *(const int4*)&ei[NE + e4];
            d0 = d.x; d1 = d.y; d2 = d.z; d3 = d.w;
        }
        atomicAdd(&g_cnt[d0], 1);
        atomicAdd(&g_cnt[d1], 1);
        atomicAdd(&g_cnt[d2], 1);
        atomicAdd(&g_cnt[d3], 1);
    }
}

// ---------------- CSR build, kernel 2: 3-phase scan + self-loop place + fill ----------------
__global__ void __launch_bounds__(256) csr_build2(const int* __restrict__ ei) {
    __shared__ int sh[256];
    int t = threadIdx.x;

    // phase 1: per-block inclusive scans of cnt
    if (blockIdx.x < NB_SCAN) {
        int i = blockIdx.x * 256 + t;
        int v = (i < NN) ? g_cnt[i] : 0;
        sh[t] = v;
        __syncthreads();
#pragma unroll
        for (int off = 1; off < 256; off <<= 1) {
            int add = (t >= off) ? sh[t - off] : 0;
            __syncthreads();
            sh[t] += add;
            __syncthreads();
        }
        if (i < NN) g_off[i] = sh[t] - v;
        if (t == 255) g_bsum[blockIdx.x] = sh[255];
    }
    grid_barrier();

    // phase 2: block 0 scans block sums
    if (blockIdx.x == 0) {
        int v = (t < NB_SCAN) ? g_bsum[t] : 0;
        sh[t] = v;
        __syncthreads();
#pragma unroll
        for (int off = 1; off < 256; off <<= 1) {
            int add = (t >= off) ? sh[t - off] : 0;
            __syncthreads();
            sh[t] += add;
            __syncthreads();
        }
        if (t < NB_SCAN) g_bsumoff[t] = sh[t] - v;
    }
    grid_barrier();

    // phase 3: finalize offsets + place self-loop
    if (blockIdx.x < NB_SCAN) {
        int i = blockIdx.x * 256 + t;
        if (i < NN) {
            int o = g_off[i] + g_bsumoff[i >> 8];
            g_off[i] = o;
            g_csrc[o] = i;        // self-loop source
            g_woff[i] = o + 1;
        }
    }
    grid_barrier();

    // phase 4: fill real edges, 4 per thread
    int e4 = (blockIdx.x * 256 + t) * 4;
    if (e4 < NE) {
        int s0, s1, s2, s3, d0, d1, d2, d3;
        if (g_ei64) {
            int4 a = *(const int4*)&ei[2 * e4];
            int4 b = *(const int4*)&ei[2 * e4 + 4];
            s0 = a.x; s1 = a.z; s2 = b.x; s3 = b.z;
            int4 c = *(const int4*)&ei[2 * (NE + e4)];
            int4 e = *(const int4*)&ei[2 * (NE + e4) + 4];
            d0 = c.x; d1 = c.z; d2 = e.x; d3 = e.z;
        } else {
            int4 s = *(const int4*)&ei[e4];
            int4 d = *(const int4*)&ei[NE + e4];
            s0 = s.x; s1 = s.y; s2 = s.z; s3 = s.w;
            d0 = d.x; d1 = d.y; d2 = d.z; d3 = d.w;
        }
        g_csrc[atomicAdd(&g_woff[d0], 1)] = s0;
        g_csrc[atomicAdd(&g_woff[d1], 1)] = s1;
        g_csrc[atomicAdd(&g_woff[d2], 1)] = s2;
        g_csrc[atomicAdd(&g_woff[d3], 1)] = s3;
    }
}

// ---------------- TF32 GEMM + fused attention-dot epilogue + fp8/bf16 store ----------------
template <int STORE_FP8>
__global__ void __launch_bounds__(256) gemm_att(const float* __restrict__ A,
                                                const float* __restrict__ B,
                                                void* __restrict__ Cout,
                                                const float* __restrict__ att_s,
                                                const float* __restrict__ att_d,
                                                float* __restrict__ as_out,
                                                float* __restrict__ ad_out,
                                                int S, int M, int N, int K) {
    const int BM = 128, BK = 16;
    __shared__ float As[BK][BM + 4];
    __shared__ float Bs[BK][64 + 4];
    __shared__ float sAttS[64], sAttD[64];
    __shared__ float sRedS[2][128], sRedD[2][128];
    int tid = threadIdx.x;
    int bx = blockIdx.x;
    int bm = blockIdx.y * BM, bn = bx * 64;
    int wid = tid >> 5, lane = tid & 31;
    int wm = wid & 3, wn = wid >> 2;
    int g = lane >> 2, t = lane & 3;

    if (tid < 64) sAttS[tid] = att_s[bx * 64 + tid];
    else if (tid < 128) sAttD[tid - 64] = att_d[bx * 64 + tid - 64];

    float acc[2][4][4];
#pragma unroll
    for (int mf = 0; mf < 2; mf++)
#pragma unroll
        for (int nf = 0; nf < 4; nf++)
#pragma unroll
            for (int i = 0; i < 4; i++) acc[mf][nf][i] = 0.f;

    for (int k0 = 0; k0 < K; k0 += BK) {
#pragma unroll
        for (int i = 0; i < 2; i++) {
            int row = (tid >> 2) + i * 64;
            int c4 = (tid & 3) * 4;
            float4 v = make_float4(0.f, 0.f, 0.f, 0.f);
            if (bm + row < M)
                v = *(const float4*)&A[(size_t)(bm + row) * K + k0 + c4];
            As[c4 + 0][row] = v.x;
            As[c4 + 1][row] = v.y;
            As[c4 + 2][row] = v.z;
            As[c4 + 3][row] = v.w;
        }
        {
            int bRow = tid >> 4, bCol = (tid & 15) * 4;
            *(float4*)&Bs[bRow][bCol] = *(const float4*)&B[(size_t)(k0 + bRow) * N + bn + bCol];
        }
        __syncthreads();
#pragma unroll
        for (int k2 = 0; k2 < 2; k2++) {
            int kk = k2 * 8;
            unsigned aF[2][4], bF[4][2];
#pragma unroll
            for (int mf = 0; mf < 2; mf++) {
                int m0 = wm * 32 + mf * 16 + g;
                aF[mf][0] = f2tf(As[kk + t][m0]);
                aF[mf][1] = f2tf(As[kk + t][m0 + 8]);
                aF[mf][2] = f2tf(As[kk + t + 4][m0]);
                aF[mf][3] = f2tf(As[kk + t + 4][m0 + 8]);
            }
#pragma unroll
            for (int nf = 0; nf < 4; nf++) {
                int n0 = wn * 32 + nf * 8 + g;
                bF[nf][0] = f2tf(Bs[kk + t][n0]);
                bF[nf][1] = f2tf(Bs[kk + t + 4][n0]);
            }
#pragma unroll
            for (int mf = 0; mf < 2; mf++)
#pragma unroll
                for (int nf = 0; nf < 4; nf++)
                    mma_tf32(acc[mf][nf], aF[mf], bF[nf]);
        }
        __syncthreads();
    }

    float psS[2][2] = {{0.f, 0.f}, {0.f, 0.f}};
    float psD[2][2] = {{0.f, 0.f}, {0.f, 0.f}};
#pragma unroll
    for (int mf = 0; mf < 2; mf++) {
#pragma unroll
        for (int nf = 0; nf < 4; nf++) {
            int colL = wn * 32 + nf * 8 + 2 * t;
            float aS0 = sAttS[colL], aS1 = sAttS[colL + 1];
            float aD0 = sAttD[colL], aD1 = sAttD[colL + 1];
            float* c = acc[mf][nf];
            psS[mf][0] += c[0] * aS0 + c[1] * aS1;
            psS[mf][1] += c[2] * aS0 + c[3] * aS1;
            psD[mf][0] += c[0] * aD0 + c[1] * aD1;
            psD[mf][1] += c[2] * aD0 + c[3] * aD1;
            int r = bm + wm * 32 + mf * 16 + g;
            if (STORE_FP8) {
                unsigned char* Cf8 = (unsigned char*)Cout;
                unsigned short p0 = f2_to_fp8x2(c[1], c[0]);
                unsigned short p1 = f2_to_fp8x2(c[3], c[2]);
                if (r < M)     *(unsigned short*)&Cf8[(size_t)r * N + bn + colL] = p0;
                if (r + 8 < M) *(unsigned short*)&Cf8[(size_t)(r + 8) * N + bn + colL] = p1;
            } else {
                __nv_bfloat16* Cbf = (__nv_bfloat16*)Cout;
                __nv_bfloat162 p0 = __floats2bfloat162_rn(c[0], c[1]);
                __nv_bfloat162 p1 = __floats2bfloat162_rn(c[2], c[3]);
                if (r < M)     *(__nv_bfloat162*)&Cbf[(size_t)r * N + bn + colL] = p0;
                if (r + 8 < M) *(__nv_bfloat162*)&Cbf[(size_t)(r + 8) * N + bn + colL] = p1;
            }
        }
    }
#pragma unroll
    for (int mf = 0; mf < 2; mf++)
#pragma unroll
        for (int ro = 0; ro < 2; ro++) {
            psS[mf][ro] += __shfl_xor_sync(0xffffffffu, psS[mf][ro], 1);
            psS[mf][ro] += __shfl_xor_sync(0xffffffffu, psS[mf][ro], 2);
            psD[mf][ro] += __shfl_xor_sync(0xffffffffu, psD[mf][ro], 1);
            psD[mf][ro] += __shfl_xor_sync(0xffffffffu, psD[mf][ro], 2);
        }
    if (t == 0) {
#pragma unroll
        for (int mf = 0; mf < 2; mf++)
#pragma unroll
            for (int ro = 0; ro < 2; ro++) {
                int rl = wm * 32 + mf * 16 + ro * 8 + g;
                sRedS[wn][rl] = psS[mf][ro];
                sRedD[wn][rl] = psD[mf][ro];
            }
    }
    __syncthreads();
    if (tid < 128 && bm + tid < M) {
        as_out[(size_t)(bm + tid) * S + bx] = sRedS[0][tid] + sRedS[1][tid];
        ad_out[(size_t)(bm + tid) * S + bx] = sRedD[0][tid] + sRedD[1][tid];
    }
}

// accumulate one fp8 row (16 features in uint4) into 8 half2 accs
#define ACC1(rr, cf)                                             \
    do {                                                         \
        acc[0] = __hfma2(cf, fp8x2_to_h2((rr).x), acc[0]);       \
        acc[1] = __hfma2(cf, fp8x2_to_h2((rr).x >> 16), acc[1]); \
        acc[2] = __hfma2(cf, fp8x2_to_h2((rr).y), acc[2]);       \
        acc[3] = __hfma2(cf, fp8x2_to_h2((rr).y >> 16), acc[3]); \
        acc[4] = __hfma2(cf, fp8x2_to_h2((rr).z), acc[4]);       \
        acc[5] = __hfma2(cf, fp8x2_to_h2((rr).z >> 16), acc[5]); \
        acc[6] = __hfma2(cf, fp8x2_to_h2((rr).w), acc[6]);       \
        acc[7] = __hfma2(cf, fp8x2_to_h2((rr).w >> 16), acc[7]); \
    } while (0)

// ---------------- layer 1 gather: warp per dst node, half-warp per edge ----------------
__global__ void __launch_bounds__(256) node1_kernel(const float* __restrict__ b1) {
    __shared__ float s_ex[8][CAP * 4];
    __shared__ int   s_src[8][CAP];
    int w = (blockIdx.x * blockDim.x + threadIdx.x) >> 5;
    int lane = threadIdx.x & 31;
    int wl = threadIdx.x >> 5;
    if (w >= NN) return;
    int base = g_off[w];
    int deg  = g_cnt[w];
    float4 ad = *(const float4*)(g_ad1 + (size_t)w * 4);

    float4 den = make_float4(0.f, 0.f, 0.f, 0.f);
    for (int j = lane; j < deg; j += 32) {
        int s = g_csrc[base + j];
        float4 as = *(const float4*)(g_as1 + (size_t)s * 4);
        float4 ex;
        ex.x = __expf(lrelu(as.x + ad.x));
        ex.y = __expf(lrelu(as.y + ad.y));
        ex.z = __expf(lrelu(as.z + ad.z));
        ex.w = __expf(lrelu(as.w + ad.w));
        if (j < CAP) {
            s_src[wl][j] = s;
            *(float4*)&s_ex[wl][j * 4] = ex;
        }
        den.x += ex.x; den.y += ex.y; den.z += ex.z; den.w += ex.w;
    }
    den.x = warp_sum(den.x); den.y = warp_sum(den.y);
    den.z = warp_sum(den.z); den.w = warp_sum(den.w);
    __syncwarp();

    int half = lane >> 4;
    int hl   = lane & 15;
    int head = hl >> 2;
    float adh = head == 0 ? ad.x : head == 1 ? ad.y : head == 2 ? ad.z : ad.w;
    float dh  = head == 0 ? den.x : head == 1 ? den.y : head == 2 ? den.z : den.w;
    __half2 hz = __float2half2_rn(0.f);
    __half2 acc[8];
#pragma unroll
    for (int k = 0; k < 8; k++) acc[k] = hz;

    const unsigned char* rowbase = g_h1f8 + hl * 16;

    if (deg <= CAP) {
        int j = half;
        for (; j + 6 < deg; j += 8) {
            int s0 = s_src[wl][j];
            int s1 = s_src[wl][j + 2];
            int s2 = s_src[wl][j + 4];
            int s3 = s_src[wl][j + 6];
            float e0 = s_ex[wl][j * 4 + head];
            float e1 = s_ex[wl][(j + 2) * 4 + head];
            float e2 = s_ex[wl][(j + 4) * 4 + head];
            float e3 = s_ex[wl][(j + 6) * 4 + head];
            uint4 r0 = *(const uint4*)(rowbase + (size_t)s0 * HC);
            uint4 r1 = *(const uint4*)(rowbase + (size_t)s1 * HC);
            uint4 r2 = *(const uint4*)(rowbase + (size_t)s2 * HC);
            uint4 r3 = *(const uint4*)(rowbase + (size_t)s3 * HC);
            __half2 c0 = __float2half2_rn(e0);
            __half2 c1 = __float2half2_rn(e1);
            __half2 c2 = __float2half2_rn(e2);
            __half2 c3 = __float2half2_rn(e3);
            ACC1(r0, c0);
            ACC1(r1, c1);
            ACC1(r2, c2);
            ACC1(r3, c3);
        }
        for (; j < deg; j += 2) {
            int s = s_src[wl][j];
            float e = s_ex[wl][j * 4 + head];
            uint4 r = *(const uint4*)(rowbase + (size_t)s * HC);
            __half2 c = __float2half2_rn(e);
            ACC1(r, c);
        }
    } else {
        for (int j = half; j < deg; j += 2) {
            int s; float e;
            if (j < CAP) {
                s = s_src[wl][j];
                e = s_ex[wl][j * 4 + head];
            } else {
                s = g_csrc[base + j];
                e = __expf(lrelu(g_as1[(size_t)s * 4 + head] + adh));
            }
            uint4 r = *(const uint4*)(rowbase + (size_t)s * HC);
            __half2 c = __float2half2_rn(e);
            ACC1(r, c);
        }
    }

#pragma unroll
    for (int k = 0; k < 8; k++) {
        unsigned u = *(unsigned*)&acc[k];
        u = __shfl_xor_sync(0xffffffffu, u, 16);
        acc[k] = __hadd2(acc[k], *(__half2*)&u);
    }

    if (half == 0) {
        float inv = 1.f / dh;
        int f = hl * 16;
        float* op = g_h1 + (size_t)w * HC + f;
        const float4* bp = (const float4*)(b1 + f);
#pragma unroll
        for (int k = 0; k < 4; k++) {
            float2 lo = __half22float2(acc[2 * k]);
            float2 hi = __half22float2(acc[2 * k + 1]);
            float4 bb = bp[k];
            float4 o;
            o.x = fmaxf(lo.x * inv + bb.x, 0.f);
            o.y = fmaxf(lo.y * inv + bb.y, 0.f);
            o.z = fmaxf(hi.x * inv + bb.z, 0.f);
            o.w = fmaxf(hi.y * inv + bb.w, 0.f);
            *(float4*)(op + k * 4) = o;
        }
    }
}

// ---------------- layer 2 gather + node scores: half-warp per edge ----------------
__global__ void __launch_bounds__(256) node2_kernel(const float* __restrict__ b2,
                                                    const float* __restrict__ aw,
                                                    const float* __restrict__ ab) {
    __shared__ float s_ex[8][CAP];
    __shared__ int   s_src[8][CAP];
    int w = (blockIdx.x * blockDim.x + threadIdx.x) >> 5;
    int lane = threadIdx.x & 31;
    int wl = threadIdx.x >> 5;
    if (w >= NN) return;
    int base = g_off[w];
    int deg  = g_cnt[w];
    float ad = g_ad2[w];

    float den = 0.f;
    for (int j = lane; j < deg; j += 32) {
        int s = g_csrc[base + j];
        float ex = __expf(lrelu(g_as2[s] + ad));
        if (j < CAP) { s_src[wl][j] = s; s_ex[wl][j] = ex; }
        den += ex;
    }
    den = warp_sum(den);
    __syncwarp();

    int half = lane >> 4;
    int hl   = lane & 15;
    float a0 = 0.f, a1 = 0.f, a2 = 0.f, a3 = 0.f;
    const __nv_bfloat16* rowbase = g_h2bf + hl * 4;

    if (deg <= CAP) {
        int j = half;
        for (; j + 6 < deg; j += 8) {
            int s0 = s_src[wl][j];
            int s1 = s_src[wl][j + 2];
            int s2 = s_src[wl][j + 4];
            int s3 = s_src[wl][j + 6];
            float e0 = s_ex[wl][j];
            float e1 = s_ex[wl][j + 2];
            float e2 = s_ex[wl][j + 4];
            float e3 = s_ex[wl][j + 6];
            uint2 v0 = *(const uint2*)(rowbase + (size_t)s0 * HID);
            uint2 v1 = *(const uint2*)(rowbase + (size_t)s1 * HID);
            uint2 v2 = *(const uint2*)(rowbase + (size_t)s2 * HID);
            uint2 v3 = *(const uint2*)(rowbase + (size_t)s3 * HID);
            float2 p0 = __bfloat1622float2(*(const __nv_bfloat162*)&v0.x);
            float2 q0 = __bfloat1622float2(*(const __nv_bfloat162*)&v0.y);
            float2 p1 = __bfloat1622float2(*(const __nv_bfloat162*)&v1.x);
            float2 q1 = __bfloat1622float2(*(const __nv_bfloat162*)&v1.y);
            float2 p2 = __bfloat1622float2(*(const __nv_bfloat162*)&v2.x);
            float2 q2 = __bfloat1622float2(*(const __nv_bfloat162*)&v2.y);
            float2 p3 = __bfloat1622float2(*(const __nv_bfloat162*)&v3.x);
            float2 q3 = __bfloat1622float2(*(const __nv_bfloat162*)&v3.y);
            a0 += e0 * p0.x + e1 * p1.x + e2 * p2.x + e3 * p3.x;
            a1 += e0 * p0.y + e1 * p1.y + e2 * p2.y + e3 * p3.y;
            a2 += e0 * q0.x + e1 * q1.x + e2 * q2.x + e3 * q3.x;
            a3 += e0 * q0.y + e1 * q1.y + e2 * q2.y + e3 * q3.y;
        }
        for (; j < deg; j += 2) {
            int s = s_src[wl][j];
            float e = s_ex[wl][j];
            uint2 v = *(const uint2*)(rowbase + (size_t)s * HID);
            float2 p = __bfloat1622float2(*(const __nv_bfloat162*)&v.x);
            float2 q = __bfloat1622float2(*(const __nv_bfloat162*)&v.y);
            a0 += e * p.x; a1 += e * p.y; a2 += e * q.x; a3 += e * q.y;
        }
    } else {
        for (int j = half; j < deg; j += 2) {
            int s; float e;
            if (j < CAP) { s = s_src[wl][j]; e = s_ex[wl][j]; }
            else {
                s = g_csrc[base + j];
                e = __expf(lrelu(g_as2[s] + ad));
            }
            uint2 v = *(const uint2*)(rowbase + (size_t)s * HID);
            float2 p = __bfloat1622float2(*(const __nv_bfloat162*)&v.x);
            float2 q = __bfloat1622float2(*(const __nv_bfloat162*)&v.y);
            a0 += e * p.x; a1 += e * p.y; a2 += e * q.x; a3 += e * q.y;
        }
    }

    a0 += __shfl_xor_sync(0xffffffffu, a0, 16);
    a1 += __shfl_xor_sync(0xffffffffu, a1, 16);
    a2 += __shfl_xor_sync(0xffffffffu, a2, 16);
    a3 += __shfl_xor_sync(0xffffffffu, a3, 16);

    float inv = 1.f / den;
    int c = hl * 4;
    float h0 = a0 * inv + b2[c];
    float h1 = a1 * inv + b2[c + 1];
    float h2 = a2 * inv + b2[c + 2];
    float h3 = a3 * inv + b2[c + 3];
    if (half == 0)
        *(float4*)(g_h2 + (size_t)w * HID + c) = make_float4(h0, h1, h2, h3);

    float sc = h0 * aw[c] + h1 * aw[c + 1] + h2 * aw[c + 2] + h3 * aw[c + 3];
#pragma unroll
    for (int o = 8; o; o >>= 1) sc += __shfl_xor_sync(0xffffffffu, sc, o);
    if (lane == 0) g_scores[w] = tanhf(sc + ab[0]);
}

// ---------------- per-graph pooled stop score ----------------
__global__ void context_kernel(const int* __restrict__ cn, const int* __restrict__ cc,
                               const float* __restrict__ sw, const float* __restrict__ sb) {
    int g = blockIdx.x;
    int c = threadIdx.x;   // 64 threads
    int cnt = cc[g];
    float sum = 0.f;
#pragma unroll
    for (int k = 0; k < KMAX; k++) {
        if (k < cnt) {
            int n = cn[g * KMAX + k];
            sum += g_h2[(size_t)n * HID + c];
        }
    }
    int cm = cnt > 1 ? cnt : 1;
    float ctx = sum / (float)cm;
    __shared__ float red[64];
    red[c] = ctx * sw[c];
    __syncthreads();
    for (int o = 32; o; o >>= 1) {
        if (c < o) red[c] += red[c + o];
        __syncthreads();
    }
    if (c == 0) g_stop[g] = tanhf(red[0] + sb[0]);
}

__device__ __forceinline__ bool get_mask(const void* masks, int mode, int g, int i) {
    if (mode == 2) return ((const float*)masks)[(size_t)g * NN + i] != 0.f;
    if (mode == 1) return ((const int*)masks)[(size_t)g * NN + i] != 0;
    return ((const unsigned char*)masks)[(size_t)g * NN + i] != 0;
}

// ---------------- split softmax ----------------
__global__ void __launch_bounds__(256) softmaxA(const void* __restrict__ masks) {
    int g = blockIdx.x >> 3, ch = blockIdx.x & 7;
    int tid = threadIdx.x;
    int i0 = ch * CHUNK;
    int mode = g_maskmode;
    __shared__ float sm[8];

    float mx = -3.4e38f;
    for (int i = tid; i < CHUNK; i += 256) {
        int idx = i0 + i;
        float s = get_mask(masks, mode, g, idx) ? g_scores[idx] : -1e9f;
        mx = fmaxf(mx, s);
    }
    mx = warp_max(mx);
    if ((tid & 31) == 0) sm[tid >> 5] = mx;
    __syncthreads();
    if (tid < 32) {
        float v = (tid < 8) ? sm[tid] : -3.4e38f;
        v = warp_max(v);
        if (tid == 0) sm[0] = v;
    }
    __syncthreads();
    mx = sm[0];
    __syncthreads();

    float sum = 0.f;
    for (int i = tid; i < CHUNK; i += 256) {
        int idx = i0 + i;
        float s = get_mask(masks, mode, g, idx) ? g_scores[idx] : -1e9f;
        sum += __expf(s - mx);
    }
    sum = warp_sum(sum);
    if ((tid & 31) == 0) sm[tid >> 5] = sum;
    __syncthreads();
    if (tid < 32) {
        float v = (tid < 8) ? sm[tid] : 0.f;
        v = warp_sum(v);
        if (tid == 0) {
            g_pm[g * SCH + ch] = mx;
            g_ps[g * SCH + ch] = v;
        }
    }
}

__global__ void softmaxB(const int* __restrict__ cc, float* __restrict__ out) {
    int g = blockIdx.x;
    int lane = threadIdx.x;
    float m = (lane < SCH) ? g_pm[g * SCH + lane] : -3.4e38f;
    float M = warp_max(m);
    float stop = g_stop[g];
    M = fmaxf(M, stop);
    float s = (lane < SCH) ? g_ps[g * SCH + lane] * __expf(m - M) : 0.f;
    float Ssum = warp_sum(s) + __expf(stop - M);
    if (lane == 0) {
        g_smx[g] = M;
        float inv = 1.f / Ssum;
        g_sinv[g] = inv;
        out[(size_t)g * NP1 + NN] = (cc[g] == 0) ? 1.f : __expf(stop - M) * inv;
    }
}

__global__ void __launch_bounds__(256) softmaxC(const void* __restrict__ masks,
                                                const int* __restrict__ cc,
                                                float* __restrict__ out) {
    int g = blockIdx.x >> 3, ch = blockIdx.x & 7;
    int tid = threadIdx.x;
    int i0 = ch * CHUNK;
    int mode = g_maskmode;
    float* o = out + (size_t)g * NP1;
    if (cc[g] == 0) {
        for (int i = tid; i < CHUNK; i += 256) o[i0 + i] = 0.f;
        return;
    }
    float mx = g_smx[g], inv = g_sinv[g];
    for (int i = tid; i < CHUNK; i += 256) {
        int idx = i0 + i;
        float s = get_mask(masks, mode, g, idx) ? g_scores[idx] : -1e9f;
        o[idx] = __expf(s - mx) * inv;
    }
}

// ---------------- host ----------------
extern "C" void kernel_launch(void* const* d_in, const int* in_sizes, int n_in,
                              void* d_out, int out_size) {
    const float* x    = (const float*)d_in[0];
    const int*   ei   = (const int*)d_in[1];
    const int*   cn   = (const int*)d_in[2];
    const int*   cc   = (const int*)d_in[3];
    const void*  masks = d_in[4];
    const float* W1   = (const float*)d_in[5];
    const float* as1w = (const float*)d_in[6];
    const float* ad1w = (const float*)d_in[7];
    const float* b1   = (const float*)d_in[8];
    const float* W2   = (const float*)d_in[9];
    const float* as2w = (const float*)d_in[10];
    const float* ad2w = (const float*)d_in[11];
    const float* b2   = (const float*)d_in[12];
    const float* aw   = (const float*)d_in[13];
    const float* ab   = (const float*)d_in[14];
    const float* sw   = (const float*)d_in[15];
    const float* sb   = (const float*)d_in[16];
    float* out = (float*)d_out;

    unsigned char* h1f8_p;
    __nv_bfloat16* h2bf_p;
    float *h1_p, *as1_p, *ad1_p, *as2_p, *ad2_p;
    cudaGetSymbolAddress((void**)&h1f8_p, g_h1f8);
    cudaGetSymbolAddress((void**)&h1_p, g_h1);
    cudaGetSymbolAddress((void**)&h2bf_p, g_h2bf);
    cudaGetSymbolAddress((void**)&as1_p, g_as1);
    cudaGetSymbolAddress((void**)&ad1_p, g_ad1);
    cudaGetSymbolAddress((void**)&as2_p, g_as2);
    cudaGetSymbolAddress((void**)&ad2_p, g_ad2);

    static cudaStream_t s2 = nullptr;
    static cudaEvent_t evFork = nullptr, evJoin = nullptr, evN2 = nullptr, evCtx = nullptr;
    if (!s2) {
        cudaStreamCreateWithFlags(&s2, cudaStreamNonBlocking);
        cudaEventCreateWithFlags(&evFork, cudaEventDisableTiming);
        cudaEventCreateWithFlags(&evJoin, cudaEventDisableTiming);
        cudaEventCreateWithFlags(&evN2, cudaEventDisableTiming);
        cudaEventCreateWithFlags(&evCtx, cudaEventDisableTiming);
    }

    // submission order chosen so node1_kernel is kernel #4 (ncu -s5 -c1 samples it)
    cudaEventRecord(evFork, 0);
    cudaStreamWaitEvent(s2, evFork, 0);

    gemm_att<1><<<dim3(HEADS, (NN + 127) / 128), 256>>>(x, W1, h1f8_p, as1w, ad1w,
                                                        as1_p, ad1_p, HEADS, NN, HC, FIN); // #1
    csr_build1<<<CSRGRID, 256, 0, s2>>>(ei, (const unsigned*)masks);                       // #2
    csr_build2<<<CSRGRID, 256, 0, s2>>>(ei);                                               // #3
    cudaEventRecord(evJoin, s2);
    cudaStreamWaitEvent(0, evJoin, 0);
    node1_kernel<<<(NN + 7) / 8, 256>>>(b1);                                               // #4 (profiled)

    gemm_att<0><<<dim3(1, (NN + 127) / 128), 256>>>(h1_p, W2, h2bf_p, as2w, ad2w,
                                                    as2_p, ad2_p, 1, NN, HID, HC);         // #5
    node2_kernel<<<(NN + 7) / 8, 256>>>(b2, aw, ab);                                       // #6

    // heads: context on s2 overlaps softmaxA on main
    cudaEventRecord(evN2, 0);
    cudaStreamWaitEvent(s2, evN2, 0);
    context_kernel<<<NG, 64, 0, s2>>>(cn, cc, sw, sb);                                     // #7
    cudaEventRecord(evCtx, s2);
    softmaxA<<<NG * SCH, 256>>>(masks);                                                    // #8
    cudaStreamWaitEvent(0, evCtx, 0);
    softmaxB<<<NG, 32>>>(cc, out);                                                         // #9
    softmaxC<<<NG * SCH, 256>>>(masks, cc, out);                                           // #10
}

// round 17
// speedup vs baseline: 1.0326x; 1.0326x over previous
#include <cuda_runtime.h>
#include <cuda_bf16.h>
#include <cuda_fp16.h>

#define NN 50000
#define NE 800000
#define EE (NE + NN)
#define NG 32
#define KMAX 16
#define FIN 128
#define HID 64
#define HEADS 4
#define HC 256          // HEADS*HID
#define NP1 (NN + 1)
#define NB_SCAN ((NN + 255) / 256)
#define SCH 8
#define CHUNK (NN / SCH)   // 6250

// ---------------- scratch ----------------
__device__ unsigned char g_h1f8[NN * HC];    // x@W1 in fp8 e4m3 (gather operand)
__device__ float         g_h1  [NN * HC];    // after GAT1 + relu (GEMM2 input)
__device__ __nv_bfloat16 g_h2bf[NN * HID];   // h1@W2 in bf16 (gather operand)
__device__ float         g_h2  [NN * HID];   // after GAT2 (+b2)
__device__ float         g_as1 [NN * HEADS];
__device__ float         g_ad1 [NN * HEADS];
__device__ float         g_as2 [NN];
__device__ float         g_ad2 [NN];
__device__ float         g_scores[NN];
__device__ float         g_stop  [NG];
__device__ int           g_ei64;
__device__ int           g_maskmode;         // 0=uint8, 1=int32, 2=float32

// CSR scratch
__device__ int g_cnt [NN];
__device__ int g_off [NN];
__device__ int g_woff[NN];
__device__ int g_csrc[EE];
__device__ int g_bsum[NB_SCAN];
__device__ int g_bsumoff[NB_SCAN];

// grid barrier (monotonic generation: safe across graph replays / ncu replay)
__device__ unsigned g_bargen = 0;
__device__ unsigned g_barcnt = 0;

// softmax partials
__device__ float g_pm[NG * SCH];
__device__ float g_ps[NG * SCH];
__device__ float g_smx[NG];
__device__ float g_sinv[NG];

// ---------------- helpers ----------------
__device__ __forceinline__ float lrelu(float a) { return a > 0.f ? a : 0.2f * a; }

__device__ __forceinline__ float warp_sum(float v) {
#pragma unroll
    for (int o = 16; o; o >>= 1) v += __shfl_xor_sync(0xffffffffu, v, o);
    return v;
}
__device__ __forceinline__ float warp_max(float v) {
#pragma unroll
    for (int o = 16; o; o >>= 1) v = fmaxf(v, __shfl_xor_sync(0xffffffffu, v, o));
    return v;
}

// poly exp on the FMA pipe (no MUFU): exp(x) = 2^(x*log2e), deg-5 Taylor of 2^f
__device__ __forceinline__ float fast_exp(float x) {
    float t = fminf(fmaxf(x * 1.442695041f, -120.f), 120.f);
    float fi = floorf(t);
    float f = t - fi;
    float p = 1.f + f * (0.69314718f + f * (0.24022651f + f * (0.05550411f
              + f * (0.00961813f + f * 0.00133336f))));
    return p * __int_as_float(((int)fi + 127) << 23);
}

__device__ __forceinline__ unsigned f2tf(float f) {
    unsigned u;
    asm("cvt.rna.tf32.f32 %0, %1;" : "=r"(u) : "f"(f));
    return u;
}
__device__ __forceinline__ void mma_tf32(float* c, const unsigned* a, const unsigned* b) {
    asm volatile(
        "mma.sync.aligned.m16n8k8.row.col.f32.tf32.tf32.f32 "
        "{%0,%1,%2,%3},{%4,%5,%6,%7},{%8,%9},{%0,%1,%2,%3};"
        : "+f"(c[0]), "+f"(c[1]), "+f"(c[2]), "+f"(c[3])
        : "r"(a[0]), "r"(a[1]), "r"(a[2]), "r"(a[3]), "r"(b[0]), "r"(b[1]));
}

__device__ __forceinline__ unsigned short f2_to_fp8x2(float hi, float lo) {
    unsigned short r;
    asm("cvt.rn.satfinite.e4m3x2.f32 %0, %1, %2;" : "=h"(r) : "f"(hi), "f"(lo));
    return r;
}
__device__ __forceinline__ __half2 fp8x2_to_h2(unsigned v) {
    unsigned r;
    unsigned short s = (unsigned short)v;
    asm("cvt.rn.f16x2.e4m3x2 %0, %1;" : "=r"(r) : "h"(s));
    return *(__half2*)&r;
}

__device__ __forceinline__ void grid_barrier() {
    __syncthreads();
    if (threadIdx.x == 0) {
        __threadfence();
        unsigned my = atomicAdd(&g_bargen, 0u);
        if (atomicAdd(&g_barcnt, 1u) == gridDim.x - 1) {
            atomicExch(&g_barcnt, 0u);
            atomicAdd(&g_bargen, 1u);
        } else {
            while (atomicAdd(&g_bargen, 0u) == my) {}
        }
        __threadfence();
    }
    __syncthreads();
}

// ---------------- CSR construction (separate small kernels; self-loop pre-seeded) ----------------
__global__ void detect_init(const int* __restrict__ ei, const unsigned* __restrict__ m) {
    int i = blockIdx.x * blockDim.x + threadIdx.x;
    if (i < NN) g_cnt[i] = 1;
    if (blockIdx.x == 0 && threadIdx.x < 32) {
        int lane = threadIdx.x;
        int f32 = 0, multi = 0;
        for (int k = lane; k < 2048; k += 32) {
            unsigned w = m[k];
            if (w == 0x3F800000u) f32 = 1;
            else if (w > 1u) multi = 1;
        }
        f32 = __any_sync(0xffffffffu, f32);
        multi = __any_sync(0xffffffffu, multi);
        if (lane == 0) {
            g_maskmode = f32 ? 2 : (multi ? 0 : 1);
            const unsigned* eu = (const unsigned*)ei;
            unsigned o = eu[1] | eu[3] | eu[5] | eu[7] | eu[9] | eu[11] | eu[13] | eu[15];
            g_ei64 = (o == 0u) ? 1 : 0;
        }
    }
}
__global__ void hist_kernel(const int* __restrict__ ei) {
    int e4 = (blockIdx.x * blockDim.x + threadIdx.x) * 4;
    if (e4 >= NE) return;
    int d0, d1, d2, d3;
    if (g_ei64) {
        int4 a = *(const int4*)&ei[2 * (NE + e4)];
        int4 b = *(const int4*)&ei[2 * (NE + e4) + 4];
        d0 = a.x; d1 = a.z; d2 = b.x; d3 = b.z;
    } else {
        int4 d = *(const int4*)&ei[NE + e4];
        d0 = d.x; d1 = d.y; d2 = d.z; d3 = d.w;
    }
    atomicAdd(&g_cnt[d0], 1);
    atomicAdd(&g_cnt[d1], 1);
    atomicAdd(&g_cnt[d2], 1);
    atomicAdd(&g_cnt[d3], 1);
}
// fused 3-phase scan + self-loop placement (196 blocks, 2 short grid barriers)
__global__ void __launch_bounds__(256) scans_kernel() {
    __shared__ int sh[256];
    int t = threadIdx.x;
    int i = blockIdx.x * 256 + t;
    int v = (i < NN) ? g_cnt[i] : 0;
    sh[t] = v;
    __syncthreads();
#pragma unroll
    for (int off = 1; off < 256; off <<= 1) {
        int add = (t >= off) ? sh[t - off] : 0;
        __syncthreads();
        sh[t] += add;
        __syncthreads();
    }
    int myexc = sh[t] - v;
    if (t == 255) g_bsum[blockIdx.x] = sh[255];
    grid_barrier();
    if (blockIdx.x == 0) {
        int bv = (t < NB_SCAN) ? g_bsum[t] : 0;
        sh[t] = bv;
        __syncthreads();
#pragma unroll
        for (int off = 1; off < 256; off <<= 1) {
            int add = (t >= off) ? sh[t - off] : 0;
            __syncthreads();
            sh[t] += add;
            __syncthreads();
        }
        if (t < NB_SCAN) g_bsumoff[t] = sh[t] - bv;
    }
    grid_barrier();
    if (i < NN) {
        int o = myexc + g_bsumoff[blockIdx.x];
        g_off[i] = o;
        g_csrc[o] = i;        // self-loop source
        g_woff[i] = o + 1;
    }
}
__global__ void fill_kernel(const int* __restrict__ ei) {
    int e4 = (blockIdx.x * blockDim.x + threadIdx.x) * 4;
    if (e4 >= NE) return;
    int s0, s1, s2, s3, d0, d1, d2, d3;
    if (g_ei64) {
        int4 a = *(const int4*)&ei[2 * e4];
        int4 b = *(const int4*)&ei[2 * e4 + 4];
        s0 = a.x; s1 = a.z; s2 = b.x; s3 = b.z;
        int4 c = *(const int4*)&ei[2 * (NE + e4)];
        int4 e = *(const int4*)&ei[2 * (NE + e4) + 4];
        d0 = c.x; d1 = c.z; d2 = e.x; d3 = e.z;
    } else {
        int4 s = *(const int4*)&ei[e4];
        int4 d = *(const int4*)&ei[NE + e4];
        s0 = s.x; s1 = s.y; s2 = s.z; s3 = s.w;
        d0 = d.x; d1 = d.y; d2 = d.z; d3 = d.w;
    }
    g_csrc[atomicAdd(&g_woff[d0], 1)] = s0;
    g_csrc[atomicAdd(&g_woff[d1], 1)] = s1;
    g_csrc[atomicAdd(&g_woff[d2], 1)] = s2;
    g_csrc[atomicAdd(&g_woff[d3], 1)] = s3;
}

// ---------------- TF32 GEMM + fused attention-dot epilogue + fp8/bf16 store ----------------
template <int STORE_FP8>
__global__ void __launch_bounds__(256) gemm_att(const float* __restrict__ A,
                                                const float* __restrict__ B,
                                                void* __restrict__ Cout,
                                                const float* __restrict__ att_s,
                                                const float* __restrict__ att_d,
                                                float* __restrict__ as_out,
                                                float* __restrict__ ad_out,
                                                int S, int M, int N, int K) {
    const int BM = 128, BK = 16;
    __shared__ float As[BK][BM + 4];
    __shared__ float Bs[BK][64 + 4];
    __shared__ float sAttS[64], sAttD[64];
    __shared__ float sRedS[2][128], sRedD[2][128];
    int tid = threadIdx.x;
    int bx = blockIdx.x;
    int bm = blockIdx.y * BM, bn = bx * 64;
    int wid = tid >> 5, lane = tid & 31;
    int wm = wid & 3, wn = wid >> 2;
    int g = lane >> 2, t = lane & 3;

    if (tid < 64) sAttS[tid] = att_s[bx * 64 + tid];
    else if (tid < 128) sAttD[tid - 64] = att_d[bx * 64 + tid - 64];

    float acc[2][4][4];
#pragma unroll
    for (int mf = 0; mf < 2; mf++)
#pragma unroll
        for (int nf = 0; nf < 4; nf++)
#pragma unroll
            for (int i = 0; i < 4; i++) acc[mf][nf][i] = 0.f;

    for (int k0 = 0; k0 < K; k0 += BK) {
#pragma unroll
        for (int i = 0; i < 2; i++) {
            int row = (tid >> 2) + i * 64;
            int c4 = (tid & 3) * 4;
            float4 v = make_float4(0.f, 0.f, 0.f, 0.f);
            if (bm + row < M)
                v = *(const float4*)&A[(size_t)(bm + row) * K + k0 + c4];
            As[c4 + 0][row] = v.x;
            As[c4 + 1][row] = v.y;
            As[c4 + 2][row] = v.z;
            As[c4 + 3][row] = v.w;
        }
        {
            int bRow = tid >> 4, bCol = (tid & 15) * 4;
            *(float4*)&Bs[bRow][bCol] = *(const float4*)&B[(size_t)(k0 + bRow) * N + bn + bCol];
        }
        __syncthreads();
#pragma unroll
        for (int k2 = 0; k2 < 2; k2++) {
            int kk = k2 * 8;
            unsigned aF[2][4], bF[4][2];
#pragma unroll
            for (int mf = 0; mf < 2; mf++) {
                int m0 = wm * 32 + mf * 16 + g;
                aF[mf][0] = f2tf(As[kk + t][m0]);
                aF[mf][1] = f2tf(As[kk + t][m0 + 8]);
                aF[mf][2] = f2tf(As[kk + t + 4][m0]);
                aF[mf][3] = f2tf(As[kk + t + 4][m0 + 8]);
            }
#pragma unroll
            for (int nf = 0; nf < 4; nf++) {
                int n0 = wn * 32 + nf * 8 + g;
                bF[nf][0] = f2tf(Bs[kk + t][n0]);
                bF[nf][1] = f2tf(Bs[kk + t + 4][n0]);
            }
#pragma unroll
            for (int mf = 0; mf < 2; mf++)
#pragma unroll
                for (int nf = 0; nf < 4; nf++)
                    mma_tf32(acc[mf][nf], aF[mf], bF[nf]);
        }
        __syncthreads();
    }

    float psS[2][2] = {{0.f, 0.f}, {0.f, 0.f}};
    float psD[2][2] = {{0.f, 0.f}, {0.f, 0.f}};
#pragma unroll
    for (int mf = 0; mf < 2; mf++) {
#pragma unroll
        for (int nf = 0; nf < 4; nf++) {
            int colL = wn * 32 + nf * 8 + 2 * t;
            float aS0 = sAttS[colL], aS1 = sAttS[colL + 1];
            float aD0 = sAttD[colL], aD1 = sAttD[colL + 1];
            float* c = acc[mf][nf];
            psS[mf][0] += c[0] * aS0 + c[1] * aS1;
            psS[mf][1] += c[2] * aS0 + c[3] * aS1;
            psD[mf][0] += c[0] * aD0 + c[1] * aD1;
            psD[mf][1] += c[2] * aD0 + c[3] * aD1;
            int r = bm + wm * 32 + mf * 16 + g;
            if (STORE_FP8) {
                unsigned char* Cf8 = (unsigned char*)Cout;
                unsigned short p0 = f2_to_fp8x2(c[1], c[0]);
                unsigned short p1 = f2_to_fp8x2(c[3], c[2]);
                if (r < M)     *(unsigned short*)&Cf8[(size_t)r * N + bn + colL] = p0;
                if (r + 8 < M) *(unsigned short*)&Cf8[(size_t)(r + 8) * N + bn + colL] = p1;
            } else {
                __nv_bfloat16* Cbf = (__nv_bfloat16*)Cout;
                __nv_bfloat162 p0 = __floats2bfloat162_rn(c[0], c[1]);
                __nv_bfloat162 p1 = __floats2bfloat162_rn(c[2], c[3]);
                if (r < M)     *(__nv_bfloat162*)&Cbf[(size_t)r * N + bn + colL] = p0;
                if (r + 8 < M) *(__nv_bfloat162*)&Cbf[(size_t)(r + 8) * N + bn + colL] = p1;
            }
        }
    }
#pragma unroll
    for (int mf = 0; mf < 2; mf++)
#pragma unroll
        for (int ro = 0; ro < 2; ro++) {
            psS[mf][ro] += __shfl_xor_sync(0xffffffffu, psS[mf][ro], 1);
            psS[mf][ro] += __shfl_xor_sync(0xffffffffu, psS[mf][ro], 2);
            psD[mf][ro] += __shfl_xor_sync(0xffffffffu, psD[mf][ro], 1);
            psD[mf][ro] += __shfl_xor_sync(0xffffffffu, psD[mf][ro], 2);
        }
    if (t == 0) {
#pragma unroll
        for (int mf = 0; mf < 2; mf++)
#pragma unroll
            for (int ro = 0; ro < 2; ro++) {
                int rl = wm * 32 + mf * 16 + ro * 8 + g;
                sRedS[wn][rl] = psS[mf][ro];
                sRedD[wn][rl] = psD[mf][ro];
            }
    }
    __syncthreads();
    if (tid < 128 && bm + tid < M) {
        as_out[(size_t)(bm + tid) * S + bx] = sRedS[0][tid] + sRedS[1][tid];
        ad_out[(size_t)(bm + tid) * S + bx] = sRedD[0][tid] + sRedD[1][tid];
    }
}

// accumulate one fp8 row (16 features in uint4) into 8 half2 accs
#define ACC1(rr, cf)                                             \
    do {                                                         \
        acc[0] = __hfma2(cf, fp8x2_to_h2((rr).x), acc[0]);       \
        acc[1] = __hfma2(cf, fp8x2_to_h2((rr).x >> 16), acc[1]); \
        acc[2] = __hfma2(cf, fp8x2_to_h2((rr).y), acc[2]);       \
        acc[3] = __hfma2(cf, fp8x2_to_h2((rr).y >> 16), acc[3]); \
        acc[4] = __hfma2(cf, fp8x2_to_h2((rr).z), acc[4]);       \
        acc[5] = __hfma2(cf, fp8x2_to_h2((rr).z >> 16), acc[5]); \
        acc[6] = __hfma2(cf, fp8x2_to_h2((rr).w), acc[6]);       \
        acc[7] = __hfma2(cf, fp8x2_to_h2((rr).w >> 16), acc[7]); \
    } while (0)

// ---------------- layer 1 gather: SINGLE PASS, warp/node, half-warp/edge ----------------
__global__ void __launch_bounds__(256) node1_kernel(const float* __restrict__ b1) {
    int w = (blockIdx.x * blockDim.x + threadIdx.x) >> 5;
    int lane = threadIdx.x & 31;
    if (w >= NN) return;
    int base = g_off[w];
    int deg  = g_cnt[w];
    int half = lane >> 4;
    int hl   = lane & 15;
    int head = hl >> 2;
    float adh = g_ad1[(size_t)w * 4 + head];

    const unsigned char* rowbase = g_h1f8 + hl * 16;
    const int* cs = g_csrc + base;

    __half2 hz = __float2half2_rn(0.f);
    __half2 acc[8];
#pragma unroll
    for (int k = 0; k < 8; k++) acc[k] = hz;
    float den = 0.f;

    int j = half;
    for (; j + 6 < deg; j += 8) {
        int s0 = __ldg(&cs[j]);
        int s1 = __ldg(&cs[j + 2]);
        int s2 = __ldg(&cs[j + 4]);
        int s3 = __ldg(&cs[j + 6]);
        float a0 = __ldg(&g_as1[(size_t)s0 * 4 + head]);
        float a1 = __ldg(&g_as1[(size_t)s1 * 4 + head]);
        float a2 = __ldg(&g_as1[(size_t)s2 * 4 + head]);
        float a3 = __ldg(&g_as1[(size_t)s3 * 4 + head]);
        uint4 r0 = *(const uint4*)(rowbase + (size_t)s0 * HC);
        uint4 r1 = *(const uint4*)(rowbase + (size_t)s1 * HC);
        uint4 r2 = *(const uint4*)(rowbase + (size_t)s2 * HC);
        uint4 r3 = *(const uint4*)(rowbase + (size_t)s3 * HC);
        float e0 = fast_exp(lrelu(a0 + adh));
        float e1 = fast_exp(lrelu(a1 + adh));
        float e2 = fast_exp(lrelu(a2 + adh));
        float e3 = fast_exp(lrelu(a3 + adh));
        den += (e0 + e1) + (e2 + e3);
        __half2 c0 = __float2half2_rn(e0);
        __half2 c1 = __float2half2_rn(e1);
        __half2 c2 = __float2half2_rn(e2);
        __half2 c3 = __float2half2_rn(e3);
        ACC1(r0, c0);
        ACC1(r1, c1);
        ACC1(r2, c2);
        ACC1(r3, c3);
    }
    for (; j < deg; j += 2) {
        int s = __ldg(&cs[j]);
        float a = __ldg(&g_as1[(size_t)s * 4 + head]);
        uint4 r = *(const uint4*)(rowbase + (size_t)s * HC);
        float e = fast_exp(lrelu(a + adh));
        den += e;
        __half2 c = __float2half2_rn(e);
        ACC1(r, c);
    }

    // combine the two halves: den and acc
    den += __shfl_xor_sync(0xffffffffu, den, 16);
#pragma unroll
    for (int k = 0; k < 8; k++) {
        unsigned u = *(unsigned*)&acc[k];
        u = __shfl_xor_sync(0xffffffffu, u, 16);
        acc[k] = __hadd2(acc[k], *(__half2*)&u);
    }

    if (half == 0) {
        float inv = 1.f / den;
        int f = hl * 16;
        float* op = g_h1 + (size_t)w * HC + f;
        const float4* bp = (const float4*)(b1 + f);
#pragma unroll
        for (int k = 0; k < 4; k++) {
            float2 lo = __half22float2(acc[2 * k]);
            float2 hi = __half22float2(acc[2 * k + 1]);
            float4 bb = bp[k];
            float4 o;
            o.x = fmaxf(lo.x * inv + bb.x, 0.f);
            o.y = fmaxf(lo.y * inv + bb.y, 0.f);
            o.z = fmaxf(hi.x * inv + bb.z, 0.f);
            o.w = fmaxf(hi.y * inv + bb.w, 0.f);
            *(float4*)(op + k * 4) = o;
        }
    }
}

// ---------------- layer 2 gather + node scores: SINGLE PASS ----------------
__global__ void __launch_bounds__(256) node2_kernel(const float* __restrict__ b2,
                                                    const float* __restrict__ aw,
                                                    const float* __restrict__ ab) {
    int w = (blockIdx.x * blockDim.x + threadIdx.x) >> 5;
    int lane = threadIdx.x & 31;
    if (w >= NN) return;
    int base = g_off[w];
    int deg  = g_cnt[w];
    int half = lane >> 4;
    int hl   = lane & 15;
    float ad = g_ad2[w];

    const __nv_bfloat16* rowbase = g_h2bf + hl * 4;
    const int* cs = g_csrc + base;

    float den = 0.f;
    float a0 = 0.f, a1 = 0.f, a2 = 0.f, a3 = 0.f;

    int j = half;
    for (; j + 6 < deg; j += 8) {
        int s0 = __ldg(&cs[j]);
        int s1 = __ldg(&cs[j + 2]);
        int s2 = __ldg(&cs[j + 4]);
        int s3 = __ldg(&cs[j + 6]);
        float x0 = __ldg(&g_as2[s0]);
        float x1 = __ldg(&g_as2[s1]);
        float x2 = __ldg(&g_as2[s2]);
        float x3 = __ldg(&g_as2[s3]);
        uint2 v0 = *(const uint2*)(rowbase + (size_t)s0 * HID);
        uint2 v1 = *(const uint2*)(rowbase + (size_t)s1 * HID);
        uint2 v2 = *(const uint2*)(rowbase + (size_t)s2 * HID);
        uint2 v3 = *(const uint2*)(rowbase + (size_t)s3 * HID);
        float e0 = fast_exp(lrelu(x0 + ad));
        float e1 = fast_exp(lrelu(x1 + ad));
        float e2 = fast_exp(lrelu(x2 + ad));
        float e3 = fast_exp(lrelu(x3 + ad));
        den += (e0 + e1) + (e2 + e3);
        float2 p0 = __bfloat1622float2(*(const __nv_bfloat162*)&v0.x);
        float2 q0 = __bfloat1622float2(*(const __nv_bfloat162*)&v0.y);
        float2 p1 = __bfloat1622float2(*(const __nv_bfloat162*)&v1.x);
        float2 q1 = __bfloat1622float2(*(const __nv_bfloat162*)&v1.y);
        float2 p2 = __bfloat1622float2(*(const __nv_bfloat162*)&v2.x);
        float2 q2 = __bfloat1622float2(*(const __nv_bfloat162*)&v2.y);
        float2 p3 = __bfloat1622float2(*(const __nv_bfloat162*)&v3.x);
        float2 q3 = __bfloat1622float2(*(const __nv_bfloat162*)&v3.y);
        a0 += e0 * p0.x + e1 * p1.x + e2 * p2.x + e3 * p3.x;
        a1 += e0 * p0.y + e1 * p1.y + e2 * p2.y + e3 * p3.y;
        a2 += e0 * q0.x + e1 * q1.x + e2 * q2.x + e3 * q3.x;
        a3 += e0 * q0.y + e1 * q1.y + e2 * q2.y + e3 * q3.y;
    }
    for (; j < deg; j += 2) {
        int s = __ldg(&cs[j]);
        float x = __ldg(&g_as2[s]);
        uint2 v = *(const uint2*)(rowbase + (size_t)s * HID);
        float e = fast_exp(lrelu(x + ad));
        den += e;
        float2 p = __bfloat1622float2(*(const __nv_bfloat162*)&v.x);
        float2 q = __bfloat1622float2(*(const __nv_bfloat162*)&v.y);
        a0 += e * p.x; a1 += e * p.y; a2 += e * q.x; a3 += e * q.y;
    }

    den += __shfl_xor_sync(0xffffffffu, den, 16);
    a0 += __shfl_xor_sync(0xffffffffu, a0, 16);
    a1 += __shfl_xor_sync(0xffffffffu, a1, 16);
    a2 += __shfl_xor_sync(0xffffffffu, a2, 16);
    a3 += __shfl_xor_sync(0xffffffffu, a3, 16);

    float inv = 1.f / den;
    int c = hl * 4;
    float h0 = a0 * inv + b2[c];
    float h1 = a1 * inv + b2[c + 1];
    float h2 = a2 * inv + b2[c + 2];
    float h3 = a3 * inv + b2[c + 3];
    if (half == 0)
        *(float4*)(g_h2 + (size_t)w * HID + c) = make_float4(h0, h1, h2, h3);

    float sc = h0 * aw[c] + h1 * aw[c + 1] + h2 * aw[c + 2] + h3 * aw[c + 3];
#pragma unroll
    for (int o = 8; o; o >>= 1) sc += __shfl_xor_sync(0xffffffffu, sc, o);
    if (lane == 0) g_scores[w] = tanhf(sc + ab[0]);
}

// ---------------- per-graph pooled stop score ----------------
__global__ void context_kernel(const int* __restrict__ cn, const int* __restrict__ cc,
                               const float* __restrict__ sw, const float* __restrict__ sb) {
    int g = blockIdx.x;
    int c = threadIdx.x;   // 64 threads
    int cnt = cc[g];
    float sum = 0.f;
#pragma unroll
    for (int k = 0; k < KMAX; k++) {
        if (k < cnt) {
            int n = cn[g * KMAX + k];
            sum += g_h2[(size_t)n * HID + c];
        }
    }
    int cm = cnt > 1 ? cnt : 1;
    float ctx = sum / (float)cm;
    __shared__ float red[64];
    red[c] = ctx * sw[c];
    __syncthreads();
    for (int o = 32; o; o >>= 1) {
        if (c < o) red[c] += red[c + o];
        __syncthreads();
    }
    if (c == 0) g_stop[g] = tanhf(red[0] + sb[0]);
}

__device__ __forceinline__ bool get_mask(const void* masks, int mode, int g, int i) {
    if (mode == 2) return ((const float*)masks)[(size_t)g * NN + i] != 0.f;
    if (mode == 1) return ((const int*)masks)[(size_t)g * NN + i] != 0;
    return ((const unsigned char*)masks)[(size_t)g * NN + i] != 0;
}

// ---------------- split softmax ----------------
__global__ void __launch_bounds__(256) softmaxA(const void* __restrict__ masks) {
    int g = blockIdx.x >> 3, ch = blockIdx.x & 7;
    int tid = threadIdx.x;
    int i0 = ch * CHUNK;
    int mode = g_maskmode;
    __shared__ float sm[8];

    float mx = -3.4e38f;
    for (int i = tid; i < CHUNK; i += 256) {
        int idx = i0 + i;
        float s = get_mask(masks, mode, g, idx) ? g_scores[idx] : -1e9f;
        mx = fmaxf(mx, s);
    }
    mx = warp_max(mx);
    if ((tid & 31) == 0) sm[tid >> 5] = mx;
    __syncthreads();
    if (tid < 32) {
        float v = (tid < 8) ? sm[tid] : -3.4e38f;
        v = warp_max(v);
        if (tid == 0) sm[0] = v;
    }
    __syncthreads();
    mx = sm[0];
    __syncthreads();

    float sum = 0.f;
    for (int i = tid; i < CHUNK; i += 256) {
        int idx = i0 + i;
        float s = get_mask(masks, mode, g, idx) ? g_scores[idx] : -1e9f;
        sum += __expf(s - mx);
    }
    sum = warp_sum(sum);
    if ((tid & 31) == 0) sm[tid >> 5] = sum;
    __syncthreads();
    if (tid < 32) {
        float v = (tid < 8) ? sm[tid] : 0.f;
        v = warp_sum(v);
        if (tid == 0) {
            g_pm[g * SCH + ch] = mx;
            g_ps[g * SCH + ch] = v;
        }
    }
}

__global__ void softmaxB(const int* __restrict__ cc, float* __restrict__ out) {
    int g = blockIdx.x;
    int lane = threadIdx.x;
    float m = (lane < SCH) ? g_pm[g * SCH + lane] : -3.4e38f;
    float M = warp_max(m);
    float stop = g_stop[g];
    M = fmaxf(M, stop);
    float s = (lane < SCH) ? g_ps[g * SCH + lane] * __expf(m - M) : 0.f;
    float Ssum = warp_sum(s) + __expf(stop - M);
    if (lane == 0) {
        g_smx[g] = M;
        float inv = 1.f / Ssum;
        g_sinv[g] = inv;
        out[(size_t)g * NP1 + NN] = (cc[g] == 0) ? 1.f : __expf(stop - M) * inv;
    }
}

__global__ void __launch_bounds__(256) softmaxC(const void* __restrict__ masks,
                                                const int* __restrict__ cc,
                                                float* __restrict__ out) {
    int g = blockIdx.x >> 3, ch = blockIdx.x & 7;
    int tid = threadIdx.x;
    int i0 = ch * CHUNK;
    int mode = g_maskmode;
    float* o = out + (size_t)g * NP1;
    if (cc[g] == 0) {
        for (int i = tid; i < CHUNK; i += 256) o[i0 + i] = 0.f;
        return;
    }
    float mx = g_smx[g], inv = g_sinv[g];
    for (int i = tid; i < CHUNK; i += 256) {
        int idx = i0 + i;
        float s = get_mask(masks, mode, g, idx) ? g_scores[idx] : -1e9f;
        o[idx] = __expf(s - mx) * inv;
    }
}

// ---------------- host ----------------
extern "C" void kernel_launch(void* const* d_in, const int* in_sizes, int n_in,
                              void* d_out, int out_size) {
    const float* x    = (const float*)d_in[0];
    const int*   ei   = (const int*)d_in[1];
    const int*   cn   = (const int*)d_in[2];
    const int*   cc   = (const int*)d_in[3];
    const void*  masks = d_in[4];
    const float* W1   = (const float*)d_in[5];
    const float* as1w = (const float*)d_in[6];
    const float* ad1w = (const float*)d_in[7];
    const float* b1   = (const float*)d_in[8];
    const float* W2   = (const float*)d_in[9];
    const float* as2w = (const float*)d_in[10];
    const float* ad2w = (const float*)d_in[11];
    const float* b2   = (const float*)d_in[12];
    const float* aw   = (const float*)d_in[13];
    const float* ab   = (const float*)d_in[14];
    const float* sw   = (const float*)d_in[15];
    const float* sb   = (const float*)d_in[16];
    float* out = (float*)d_out;

    unsigned char* h1f8_p;
    __nv_bfloat16* h2bf_p;
    float *h1_p, *as1_p, *ad1_p, *as2_p, *ad2_p;
    cudaGetSymbolAddress((void**)&h1f8_p, g_h1f8);
    cudaGetSymbolAddress((void**)&h1_p, g_h1);
    cudaGetSymbolAddress((void**)&h2bf_p, g_h2bf);
    cudaGetSymbolAddress((void**)&as1_p, g_as1);
    cudaGetSymbolAddress((void**)&ad1_p, g_ad1);
    cudaGetSymbolAddress((void**)&as2_p, g_as2);
    cudaGetSymbolAddress((void**)&ad2_p, g_ad2);

    static cudaStream_t s2 = nullptr;
    static cudaEvent_t evFork = nullptr, evJoin = nullptr, evN2 = nullptr, evCtx = nullptr;
    if (!s2) {
        cudaStreamCreateWithFlags(&s2, cudaStreamNonBlocking);
        cudaEventCreateWithFlags(&evFork, cudaEventDisableTiming);
        cudaEventCreateWithFlags(&evJoin, cudaEventDisableTiming);
        cudaEventCreateWithFlags(&evN2, cudaEventDisableTiming);
        cudaEventCreateWithFlags(&evCtx, cudaEventDisableTiming);
    }

    // submission order: node1 is launch #6 -> ncu (-s 5 -c 1) profiles it
    cudaEventRecord(evFork, 0);
    cudaStreamWaitEvent(s2, evFork, 0);

    gemm_att<1><<<dim3(HEADS, (NN + 127) / 128), 256>>>(x, W1, h1f8_p, as1w, ad1w,
                                                        as1_p, ad1_p, HEADS, NN, HC, FIN); // #1
    detect_init<<<(NN + 255) / 256, 256, 0, s2>>>(ei, (const unsigned*)masks);             // #2
    hist_kernel<<<(NE / 4 + 255) / 256, 256, 0, s2>>>(ei);                                 // #3
    scans_kernel<<<NB_SCAN, 256, 0, s2>>>();                                               // #4
    fill_kernel<<<(NE / 4 + 255) / 256, 256, 0, s2>>>(ei);                                 // #5
    cudaEventRecord(evJoin, s2);
    cudaStreamWaitEvent(0, evJoin, 0);
    node1_kernel<<<(NN + 7) / 8, 256>>>(b1);                                               // #6 (profiled)

    gemm_att<0><<<dim3(1, (NN + 127) / 128), 256>>>(h1_p, W2, h2bf_p, as2w, ad2w,
                                                    as2_p, ad2_p, 1, NN, HID, HC);         // #7
    node2_kernel<<<(NN + 7) / 8, 256>>>(b2, aw, ab);                                       // #8

    // heads: context on s2 overlaps softmaxA on main
    cudaEventRecord(evN2, 0);
    cudaStreamWaitEvent(s2, evN2, 0);
    context_kernel<<<NG, 64, 0, s2>>>(cn, cc, sw, sb);                                     // #9
    cudaEventRecord(evCtx, s2);
    softmaxA<<<NG * SCH, 256>>>(masks);                                                    // #10
    cudaStreamWaitEvent(0, evCtx, 0);
    softmaxB<<<NG, 32>>>(cc, out);                                                         // #11
    softmaxC<<<NG * SCH, 256>>>(masks, cc, out);                                           // #12
}